// round 1
// baseline (speedup 1.0000x reference)
#include <cuda_runtime.h>
#include <math.h>

#define NBLK 592
#define NTHR 256
#define SAMP_BINS 1024
#define FINE_BINS 1024
#define MAX_POS 131072
#define SAMP_LO (-12.0f)
#define SAMP_W  (24.0f / SAMP_BINS)

static __device__ int                g_pos_n;
static __device__ float              g_pos_list[MAX_POS];
static __device__ int                g_samp_hist[SAMP_BINS];
static __device__ float              g_Tlo, g_Thi;
static __device__ long long          g_nhns;
static __device__ unsigned long long g_cnt_above;
static __device__ double             g_loss_above, g_sig_above;
static __device__ int                g_fine_cnt[FINE_BINS];
static __device__ float              g_fine_loss[FINE_BINS];
static __device__ float              g_fine_sig[FINE_BINS];

__device__ __forceinline__ float softplusf(float x) {
    // logaddexp(0, x) = max(x,0) + log1p(exp(-|x|)), numerically stable
    return fmaxf(x, 0.0f) + log1pf(__expf(-fabsf(x)));
}
__device__ __forceinline__ float sigmf(float x) {
    return 1.0f / (1.0f + __expf(-x));
}

// ---------------------------------------------------------------------------
// Kernel 0: zero all global accumulators (graph replays need a fresh state)
// ---------------------------------------------------------------------------
__global__ void k_init() {
    int i = blockIdx.x * blockDim.x + threadIdx.x;
    if (i == 0) {
        g_pos_n = 0;
        g_cnt_above = 0ull;
        g_loss_above = 0.0;
        g_sig_above = 0.0;
    }
    if (i < SAMP_BINS) g_samp_hist[i] = 0;
    if (i < FINE_BINS) {
        g_fine_cnt[i] = 0;
        g_fine_loss[i] = 0.0f;
        g_fine_sig[i] = 0.0f;
    }
}

// ---------------------------------------------------------------------------
// Kernel 1: collect positives + sampled coarse histogram of negative preds
// ---------------------------------------------------------------------------
__global__ __launch_bounds__(NTHR) void k_pass1(
    const float4* __restrict__ preds4, const int4* __restrict__ targs4, int n4,
    const float* __restrict__ preds, const int* __restrict__ targs, int n)
{
    __shared__ int sh[SAMP_BINS];
    for (int i = threadIdx.x; i < SAMP_BINS; i += blockDim.x) sh[i] = 0;
    __syncthreads();

    const float scale = (float)SAMP_BINS / 24.0f;
    int stride = gridDim.x * blockDim.x;
    for (int i = blockIdx.x * blockDim.x + threadIdx.x; i < n4; i += stride) {
        float4 p = preds4[i];
        int4   t = targs4[i];
        if (t.x | t.y | t.z | t.w) {  // positives are ~0.1%: rare branch
            if (t.x) { int id = atomicAdd(&g_pos_n, 1); if (id < MAX_POS) g_pos_list[id] = p.x; }
            if (t.y) { int id = atomicAdd(&g_pos_n, 1); if (id < MAX_POS) g_pos_list[id] = p.y; }
            if (t.z) { int id = atomicAdd(&g_pos_n, 1); if (id < MAX_POS) g_pos_list[id] = p.z; }
            if (t.w) { int id = atomicAdd(&g_pos_n, 1); if (id < MAX_POS) g_pos_list[id] = p.w; }
        }
        if ((i & 15) == 0) {  // 1-in-16 float4s => 1/16 element sample
            if (!t.x) { int b = (int)((p.x - SAMP_LO) * scale); b = max(0, min(SAMP_BINS - 1, b)); atomicAdd(&sh[b], 1); }
            if (!t.y) { int b = (int)((p.y - SAMP_LO) * scale); b = max(0, min(SAMP_BINS - 1, b)); atomicAdd(&sh[b], 1); }
            if (!t.z) { int b = (int)((p.z - SAMP_LO) * scale); b = max(0, min(SAMP_BINS - 1, b)); atomicAdd(&sh[b], 1); }
            if (!t.w) { int b = (int)((p.w - SAMP_LO) * scale); b = max(0, min(SAMP_BINS - 1, b)); atomicAdd(&sh[b], 1); }
        }
    }
    // scalar tail (N=256^3 is divisible by 4, but stay safe)
    if (blockIdx.x == 0 && threadIdx.x == 0) {
        for (int i = 4 * n4; i < n; i++) {
            if (targs[i]) { int id = atomicAdd(&g_pos_n, 1); if (id < MAX_POS) g_pos_list[id] = preds[i]; }
        }
    }
    __syncthreads();
    for (int i = threadIdx.x; i < SAMP_BINS; i += blockDim.x) {
        int c = sh[i];
        if (c) atomicAdd(&g_samp_hist[i], c);
    }
}

// ---------------------------------------------------------------------------
// Kernel 2 (1 block, 1024 thr): compute n_hns, pick bracketing window [Tlo,Thi]
// ---------------------------------------------------------------------------
__global__ void k_pick(long long N) {
    __shared__ long long suf[SAMP_BINS];
    __shared__ int sh_bhi, sh_blo;
    int t = threadIdx.x;
    suf[t] = (long long)g_samp_hist[t];
    if (t == 0) { sh_bhi = SAMP_BINS; sh_blo = -1; }
    __syncthreads();
    // inclusive suffix sum (Hillis-Steele)
    for (int off = 1; off < SAMP_BINS; off <<= 1) {
        long long v = (t + off < SAMP_BINS) ? suf[t + off] : 0;
        __syncthreads();
        suf[t] += v;
        __syncthreads();
    }
    long long n_pos = min(g_pos_n, MAX_POS);
    long long n_neg = N - n_pos;
    long long nhns = (n_pos > 0) ? min(n_pos * 30LL, n_neg)
                                 : (long long)(0.1 * (double)n_neg);
    // est count of negatives with pred >= left edge of bin t  (x16 sample rate)
    long long est = 16LL * suf[t];
    // margins: Thi chosen so true count_above(Thi) <= nhns for sure (0.65x),
    //          Tlo so true count_above(Tlo) >= nhns for sure (1.5x)
    if (est * 100 <= nhns * 65)  atomicMin(&sh_bhi, t);
    if (est * 10  >= nhns * 15)  atomicMax(&sh_blo, t);
    __syncthreads();
    if (t == 0) {
        int bhi = sh_bhi, blo = sh_blo;
        if (bhi > SAMP_BINS - 1) bhi = SAMP_BINS - 1;
        if (bhi < 1) bhi = 1;
        if (blo < 0) blo = 0;
        if (blo >= bhi) blo = bhi - 1;
        g_Thi = SAMP_LO + (float)bhi * SAMP_W;
        g_Tlo = SAMP_LO + (float)blo * SAMP_W;
        g_nhns = nhns;
    }
}

// ---------------------------------------------------------------------------
// Kernel 3: exact sums above Thi + fine histogram inside window (preds only)
// ---------------------------------------------------------------------------
__device__ __forceinline__ void proc_elem(float v, float Tlo, float Thi, float fscale,
                                          int& cnt, float& ls, float& ss) {
    if (v > Tlo) {
        float sp = softplusf(v);
        float sg = sigmf(v);
        if (v > Thi) {
            cnt++; ls += sp; ss += sg;
        } else {
            int fb = min((int)((v - Tlo) * fscale), FINE_BINS - 1);
            atomicAdd(&g_fine_cnt[fb], 1);
            atomicAdd(&g_fine_loss[fb], sp);
            atomicAdd(&g_fine_sig[fb], sg);
        }
    }
}

__global__ __launch_bounds__(NTHR) void k_pass2(
    const float4* __restrict__ preds4, int n4,
    const float* __restrict__ preds, int n)
{
    const float Tlo = g_Tlo, Thi = g_Thi;
    const float fscale = (float)FINE_BINS / (Thi - Tlo);
    int cnt = 0;
    float ls = 0.0f, ss = 0.0f;
    int stride = gridDim.x * blockDim.x;
    for (int i = blockIdx.x * blockDim.x + threadIdx.x; i < n4; i += stride) {
        float4 p = preds4[i];
        proc_elem(p.x, Tlo, Thi, fscale, cnt, ls, ss);
        proc_elem(p.y, Tlo, Thi, fscale, cnt, ls, ss);
        proc_elem(p.z, Tlo, Thi, fscale, cnt, ls, ss);
        proc_elem(p.w, Tlo, Thi, fscale, cnt, ls, ss);
    }
    if (blockIdx.x == 0 && threadIdx.x == 0) {
        for (int i = 4 * n4; i < n; i++)
            proc_elem(preds[i], Tlo, Thi, fscale, cnt, ls, ss);
    }
    // block reduce (cnt, ls, ss)
    __shared__ int   rc[NTHR];
    __shared__ float rl[NTHR], rs[NTHR];
    int t = threadIdx.x;
    rc[t] = cnt; rl[t] = ls; rs[t] = ss;
    __syncthreads();
    for (int off = NTHR / 2; off > 0; off >>= 1) {
        if (t < off) { rc[t] += rc[t + off]; rl[t] += rl[t + off]; rs[t] += rs[t + off]; }
        __syncthreads();
    }
    if (t == 0) {
        if (rc[0]) atomicAdd(&g_cnt_above, (unsigned long long)rc[0]);
        atomicAdd(&g_loss_above, (double)rl[0]);
        atomicAdd(&g_sig_above,  (double)rs[0]);
    }
}

// ---------------------------------------------------------------------------
// Kernel 4 (1 block, 1024 thr): positive correction, exact k-th threshold,
// final dice + mean-loss scalar
// ---------------------------------------------------------------------------
__global__ void k_final(float* __restrict__ out, int out_size) {
    __shared__ int       s_cnt[FINE_BINS];
    __shared__ float     s_loss[FINE_BINS];
    __shared__ float     s_sig[FINE_BINS];
    __shared__ long long suf[FINE_BINS];
    __shared__ double    red1[1024], red2[1024];
    __shared__ int       sh_adj_cnt;
    __shared__ double    sh_adj_loss, sh_adj_sig;
    __shared__ int       sh_bstar;
    __shared__ float     sh_result;

    int t = threadIdx.x;
    s_cnt[t]  = g_fine_cnt[t];
    s_loss[t] = g_fine_loss[t];
    s_sig[t]  = g_fine_sig[t];
    if (t == 0) { sh_adj_cnt = 0; sh_adj_loss = 0.0; sh_adj_sig = 0.0; sh_bstar = -1; }
    __syncthreads();

    const float Tlo = g_Tlo, Thi = g_Thi;
    const float fscale = (float)FINE_BINS / (Thi - Tlo);
    int n_pos = min(g_pos_n, MAX_POS);

    // positives: accumulate their loss/sigmoid, and remove them from the
    // "negative" counters (pass2 counted them because it only saw preds)
    double ploss = 0.0, psig = 0.0;
    for (int i = t; i < n_pos; i += blockDim.x) {
        float q  = g_pos_list[i];
        float sp = softplusf(q);
        float sg = sigmf(q);
        ploss += (double)(sp - q);   // loss with t=1: softplus(x) - x
        psig  += (double)sg;
        if (q > Thi) {
            atomicAdd(&sh_adj_cnt, 1);
            atomicAdd(&sh_adj_loss, (double)sp);
            atomicAdd(&sh_adj_sig,  (double)sg);
        } else if (q > Tlo) {
            int fb = min((int)((q - Tlo) * fscale), FINE_BINS - 1);
            atomicSub(&s_cnt[fb], 1);
            atomicAdd(&s_loss[fb], -sp);
            atomicAdd(&s_sig[fb],  -sg);
        }
    }
    red1[t] = ploss; red2[t] = psig;
    __syncthreads();
    for (int off = 512; off > 0; off >>= 1) {
        if (t < off) { red1[t] += red1[t + off]; red2[t] += red2[t + off]; }
        __syncthreads();
    }
    double pos_loss = red1[0];
    double pos_sig  = red2[0];
    __syncthreads();

    // suffix sum of corrected fine counts
    suf[t] = (long long)s_cnt[t];
    __syncthreads();
    for (int off = 1; off < FINE_BINS; off <<= 1) {
        long long v = (t + off < FINE_BINS) ? suf[t + off] : 0;
        __syncthreads();
        suf[t] += v;
        __syncthreads();
    }

    long long cnt_above = (long long)g_cnt_above - (long long)sh_adj_cnt;
    long long nhns = g_nhns;

    // bstar = LARGEST bin with cnt_above + suffix(bstar) >= nhns
    // (bins > bstar fully selected, partial take from bstar)
    if (cnt_above + suf[t] >= nhns) atomicMax(&sh_bstar, t);
    __syncthreads();
    int bstar = sh_bstar;

    double fl = 0.0, fs = 0.0;
    if (t > bstar) { fl = (double)s_loss[t]; fs = (double)s_sig[t]; }
    red1[t] = fl; red2[t] = fs;
    __syncthreads();
    for (int off = 512; off > 0; off >>= 1) {
        if (t < off) { red1[t] += red1[t + off]; red2[t] += red2[t + off]; }
        __syncthreads();
    }

    if (t == 0) {
        double neg_loss = g_loss_above - sh_adj_loss + red1[0];
        double neg_sig  = g_sig_above  - sh_adj_sig  + red2[0];
        if (bstar >= 0 && bstar < FINE_BINS && s_cnt[bstar] > 0) {
            long long taken = cnt_above + (suf[bstar] - (long long)s_cnt[bstar]);
            long long r = nhns - taken;
            if (r < 0) r = 0;
            if (r > (long long)s_cnt[bstar]) r = (long long)s_cnt[bstar];
            double frac = (double)r / (double)s_cnt[bstar];
            neg_loss += frac * (double)s_loss[bstar];
            neg_sig  += frac * (double)s_sig[bstar];
        }
        double total_loss = neg_loss + pos_loss;
        double mean_loss  = total_loss / (double)(nhns + (long long)n_pos);
        double inter = pos_sig;                                  // sum sigmoid*t
        double denom = neg_sig + pos_sig + (double)n_pos;        // sum sig + sum t
        double dice  = 1.0 - (2.0 * inter + 1e-10) / (denom + 1e-10);
        sh_result = (float)(dice + mean_loss);
    }
    __syncthreads();
    float r = sh_result;
    for (int i = t; i < out_size; i += blockDim.x) out[i] = r;
}

// ---------------------------------------------------------------------------
extern "C" void kernel_launch(void* const* d_in, const int* in_sizes, int n_in,
                              void* d_out, int out_size) {
    const float* preds = (const float*)d_in[0];
    const int*   targs = (const int*)d_in[1];
    int n  = in_sizes[0];
    int n4 = n / 4;

    k_init<<<4, 256>>>();
    k_pass1<<<NBLK, NTHR>>>((const float4*)preds, (const int4*)targs, n4, preds, targs, n);
    k_pick<<<1, 1024>>>((long long)n);
    k_pass2<<<NBLK, NTHR>>>((const float4*)preds, n4, preds, n);
    k_final<<<1, 1024>>>((float*)d_out, out_size);
}